// round 15
// baseline (speedup 1.0000x reference)
#include <cuda_runtime.h>
#include <cuda_bf16.h>
#include <cstdint>

// Problem constants
#define B_    32
#define U_    4096
#define D_    512
#define H_    4
#define HD_   128
#define CK_   31
#define CF_   32
#define AU_   512

#define UC    128            // u rows per CTA chunk
#define NC    (U_ / UC)      // 32 chunks per batch
#define ST    8              // rows per pipeline stage
#define NSUB  (UC / ST)      // 16
#define NSTG  4              // pipeline stages
#define KS_   64             // k-slices for the out GEMM (depth 32 each)

// ---------------- scratch (device globals) ----------------------------------
__device__ float g_KEFF[CK_ * H_];
__device__ float g_V[B_ * H_ * D_];
__device__ float g_LB[(size_t)B_ * U_ * H_];                // location bias [b][u][h]
__device__ float g_P[(size_t)B_ * U_ * H_];                 // exp(energy), [b][u][h]
__device__ float g_CTXP[(size_t)B_ * NC * H_ * D_];         // per-chunk ctx partials
__device__ float g_SP[B_ * NC * H_];                        // per-chunk sum of p
__device__ float g_CTX[B_ * H_ * D_];                       // normalized context
__device__ float g_OUTP[KS_ * B_ * AU_];                    // out GEMM partials

// ---------------- PTX helpers -----------------------------------------------
__device__ __forceinline__ uint32_t smem_u32(const void* p) {
    uint32_t a;
    asm("{ .reg .u64 t; cvta.to.shared.u64 t, %1; cvt.u32.u64 %0, t; }"
        : "=r"(a) : "l"(p));
    return a;
}
__device__ __forceinline__ void cp_async16(uint32_t dst, const void* src) {
    asm volatile("cp.async.cg.shared.global [%0], [%1], 16;"
                 :: "r"(dst), "l"(src) : "memory");
}
__device__ __forceinline__ void cp_commit() {
    asm volatile("cp.async.commit_group;" ::: "memory");
}
template <int N>
__device__ __forceinline__ void cp_wait() {
    asm volatile("cp.async.wait_group %0;" :: "n"(N) : "memory");
}
__device__ __forceinline__ void fma2(unsigned long long& d,
                                     unsigned long long a,
                                     unsigned long long b) {
    asm("fma.rn.f32x2 %0, %1, %2, %0;" : "+l"(d) : "l"(a), "l"(b));
}
__device__ __forceinline__ unsigned long long pack2(float lo, float hi) {
    unsigned long long r;
    asm("mov.b64 %0, {%1, %2};" : "=l"(r) : "f"(lo), "f"(hi));
    return r;
}
__device__ __forceinline__ float2 unpack2(unsigned long long v) {
    float2 r;
    asm("mov.b64 {%0, %1}, %2;" : "=f"(r.x), "=f"(r.y) : "l"(v));
    return r;
}

// ---------------- kernel 0: effective conv kernel ---------------------------
__global__ void keff_kernel(const float* __restrict__ ck,
                            const float* __restrict__ Wloc)
{
    int i = threadIdx.x;
    if (i < CK_ * H_) {
        int k = i >> 2, h = i & 3;
        float s = 0.f;
        #pragma unroll
        for (int f = 0; f < CF_; f++) s += ck[k * CF_ + f] * Wloc[f * H_ + h];
        g_KEFF[i] = s;
    }
}

// ---------------- kernel 1: phi & v -----------------------------------------
__global__ void phiv_kernel(const float* __restrict__ dec,
                            const float* __restrict__ Wphi,
                            const float* __restrict__ bphi,
                            const float* __restrict__ Wpsi)
{
    __shared__ float dec_sm[D_];
    __shared__ float phi_part[2][HD_];
    __shared__ float phi_sm[HD_];
    int bx = blockIdx.x;
    int b = bx >> 2, h = bx & 3;
    int tid = threadIdx.x;   // 256

    for (int i = tid; i < D_; i += 256) dec_sm[i] = dec[(size_t)b * D_ + i];
    __syncthreads();

    {
        int k = tid & 127, sl = tid >> 7;
        const float* w = Wphi + (size_t)h * D_ * HD_ + (size_t)sl * 256 * HD_ + k;
        const float* ds = dec_sm + sl * 256;
        float a0 = 0.f, a1 = 0.f, a2 = 0.f, a3 = 0.f;
        #pragma unroll 8
        for (int d = 0; d < 256; d += 4) {
            a0 += ds[d + 0] * w[(size_t)(d + 0) * HD_];
            a1 += ds[d + 1] * w[(size_t)(d + 1) * HD_];
            a2 += ds[d + 2] * w[(size_t)(d + 2) * HD_];
            a3 += ds[d + 3] * w[(size_t)(d + 3) * HD_];
        }
        phi_part[sl][k] = (a0 + a1) + (a2 + a3);
    }
    __syncthreads();
    if (tid < HD_)
        phi_sm[tid] = phi_part[0][tid] + phi_part[1][tid] + bphi[h * HD_ + tid];
    __syncthreads();

    for (int e = tid; e < D_; e += 256) {
        const float4* wp = reinterpret_cast<const float4*>(
            Wpsi + ((size_t)h * D_ + e) * HD_);
        float vv = 0.f;
        #pragma unroll 8
        for (int k4 = 0; k4 < HD_ / 4; k4++) {
            float4 ww = wp[k4];
            vv += ww.x * phi_sm[4 * k4 + 0] + ww.y * phi_sm[4 * k4 + 1]
                + ww.z * phi_sm[4 * k4 + 2] + ww.w * phi_sm[4 * k4 + 3];
        }
        g_V[(size_t)bx * D_ + e] = vv;
    }
}

// ---------------- kernel 2: location bias -----------------------------------
__global__ void lb_kernel(const float* __restrict__ prev)
{
    __shared__ float prevs[1024 + CK_ - 1];
    __shared__ float keffs[CK_ * H_];
    int z = blockIdx.x, b = blockIdx.y;
    int tid = threadIdx.x;
    int ubase = z * 1024;

    for (int i = tid; i < 1024 + CK_ - 1; i += 256) {
        int gu = ubase + i - 15;
        prevs[i] = (gu >= 0 && gu < U_) ? prev[(size_t)b * U_ + gu] : 0.f;
    }
    if (tid < CK_ * H_) keffs[tid] = g_KEFF[tid];
    __syncthreads();

    float4* outp = reinterpret_cast<float4*>(
        g_LB + ((size_t)b * U_ + ubase) * H_);
    #pragma unroll
    for (int q = 0; q < 4; q++) {
        int ul = tid + 256 * q;
        float l0 = 0.f, l1 = 0.f, l2 = 0.f, l3 = 0.f;
        #pragma unroll
        for (int k = 0; k < CK_; k++) {
            float pv = prevs[ul + k];
            l0 += pv * keffs[k * H_ + 0];
            l1 += pv * keffs[k * H_ + 1];
            l2 += pv * keffs[k * H_ + 2];
            l3 += pv * keffs[k * H_ + 3];
        }
        outp[ul] = make_float4(l0, l1, l2, l3);
    }
}

// ---------------- kernel 3 (PROFILED): fused energy+exp+context -------------
// grid (NC=32, B), 256 threads, 2 CTAs/SM, 4-stage pipeline, 1 barrier/subtile.
// Warp split: pair = warp>>1, j = warp&1; rows {pair, pair+4}; heads {2j,2j+1}.
// smem floats (68 KB): tiles 4*ST*D=16384 | pall 512 | lbs 512
// ctxred ([4][H][D]=8192 fl) aliases tiles after the main loop.
#define SMEM_F_FLOATS 17408
#define SMEM_F_BYTES (SMEM_F_FLOATS * 4)

__global__ void __launch_bounds__(256, 2)
fused_kernel(const float* __restrict__ enc)
{
    extern __shared__ float smem[];
    float* tiles  = smem;                  // 4 x 4096 floats
    float* pall   = smem + 16384;          // [uu][h]
    float* lbs    = smem + 16896;          // [uu][h]
    float* ctxred = smem;                  // ALIAS: post-loop only

    int tid  = threadIdx.x;
    int warp = tid >> 5, lane = tid & 31;
    int pair = warp >> 1, j = warp & 1;
    int b  = blockIdx.y;
    int u0 = blockIdx.x * UC;

    const float* enc_base = enc + ((size_t)b * U_ + u0) * D_;
    uint32_t tiles_s = smem_u32(tiles);

    // prologue: stage subtiles 0, 1, 2
    #pragma unroll
    for (int s = 0; s < NSTG - 1; s++) {
        uint32_t dst = tiles_s + s * (ST * D_ * 4);
        const float* src = enc_base + s * ST * D_;
        #pragma unroll
        for (int q = 0; q < 4; q++) {
            int idx = tid + 256 * q;
            cp_async16(dst + idx * 16, src + idx * 4);
        }
        cp_commit();
    }

    // stage lb for the chunk
    #pragma unroll
    for (int q = 0; q < 2; q++) {
        int idx = tid + 256 * q;
        lbs[idx] = g_LB[((size_t)b * U_ + u0) * H_ + idx];
    }

    // v for this warp's 2 heads
    ulonglong2 v2[2][4];
    #pragma unroll
    for (int g = 0; g < 2; g++) {
        const ulonglong2* vp = reinterpret_cast<const ulonglong2*>(
            g_V + (size_t)(b * H_ + 2 * j + g) * D_);
        #pragma unroll
        for (int i = 0; i < 4; i++) v2[g][i] = vp[lane + 32 * i];
    }

    unsigned long long ctx2[2][8];
    #pragma unroll
    for (int g = 0; g < 2; g++)
        #pragma unroll
        for (int i = 0; i < 8; i++) ctx2[g][i] = 0ull;

    for (int s = 0; s < NSUB; s++) {
        if (s < NSUB - 2)      cp_wait<2>();
        else if (s == NSUB - 2) cp_wait<1>();
        else                   cp_wait<0>();
        __syncthreads();   // the ONLY barrier per subtile

        // prefetch s+3 into slot (s+3)%4 (consumed at s-1; safe after barrier)
        if (s + NSTG - 1 < NSUB) {
            uint32_t dst = tiles_s + ((s + NSTG - 1) % NSTG) * (ST * D_ * 4);
            const float* src = enc_base + (s + NSTG - 1) * ST * D_;
            #pragma unroll
            for (int q = 0; q < 4; q++) {
                int idx = tid + 256 * q;
                cp_async16(dst + idx * 16, src + idx * 4);
            }
            cp_commit();
        }

        const float* tile = tiles + (s % NSTG) * (ST * D_);
        #pragma unroll
        for (int t = 0; t < 2; t++) {
            int r = pair + 4 * t;
            int uu = s * ST + r;
            const ulonglong2* row =
                reinterpret_cast<const ulonglong2*>(tile + r * D_);
            ulonglong2 X[4];
            #pragma unroll
            for (int i = 0; i < 4; i++) X[i] = row[lane + 32 * i];

            unsigned long long a2h[2] = {0ull, 0ull};
            #pragma unroll
            for (int i = 0; i < 4; i++) {
                fma2(a2h[0], X[i].x, v2[0][i].x);
                fma2(a2h[0], X[i].y, v2[0][i].y);
                fma2(a2h[1], X[i].x, v2[1][i].x);
                fma2(a2h[1], X[i].y, v2[1][i].y);
            }
            float2 f0 = unpack2(a2h[0]), f1 = unpack2(a2h[1]);
            float a0 = f0.x + f0.y, a1 = f1.x + f1.y;
            #pragma unroll
            for (int off = 16; off; off >>= 1) {
                a0 += __shfl_xor_sync(0xffffffffu, a0, off);
                a1 += __shfl_xor_sync(0xffffffffu, a1, off);
            }
            float2 lb = *reinterpret_cast<const float2*>(lbs + uu * H_ + 2 * j);
            float p0 = __expf(a0 + lb.x);
            float p1 = __expf(a1 + lb.y);
            if (lane == 0)
                *reinterpret_cast<float2*>(pall + uu * H_ + 2 * j) =
                    make_float2(p0, p1);
            unsigned long long pp0 = pack2(p0, p0);
            unsigned long long pp1 = pack2(p1, p1);
            #pragma unroll
            for (int i = 0; i < 4; i++) {
                fma2(ctx2[0][2 * i + 0], X[i].x, pp0);
                fma2(ctx2[0][2 * i + 1], X[i].y, pp0);
                fma2(ctx2[1][2 * i + 0], X[i].x, pp1);
                fma2(ctx2[1][2 * i + 1], X[i].y, pp1);
            }
        }
    }
    __syncthreads();   // compute done; tiles memory reusable (ctxred)

    // dump per-warp ctx partials: ctxred[pair][head][e]
    #pragma unroll
    for (int g = 0; g < 2; g++) {
        float4 c[4];
        #pragma unroll
        for (int i = 0; i < 4; i++) {
            float2 lo = unpack2(ctx2[g][2 * i + 0]);
            float2 hi = unpack2(ctx2[g][2 * i + 1]);
            c[i] = make_float4(lo.x, lo.y, hi.x, hi.y);
        }
        float4* cr = reinterpret_cast<float4*>(
            ctxred + (pair * H_ + 2 * j + g) * D_);
        #pragma unroll
        for (int i = 0; i < 4; i++) cr[lane + 32 * i] = c[i];
    }
    __syncthreads();

    size_t chunk = (size_t)b * NC + blockIdx.x;

    // reduce 4 pairs -> g_CTXP
    #pragma unroll
    for (int q = 0; q < 8; q++) {
        int idx = tid + 256 * q;           // [0,2048) == [h][e]
        float sum = ctxred[idx] + ctxred[H_ * D_ + idx]
                  + ctxred[2 * H_ * D_ + idx] + ctxred[3 * H_ * D_ + idx];
        g_CTXP[chunk * (H_ * D_) + idx] = sum;
    }

    // per-chunk sum of p
    if (warp < H_) {
        float sp = pall[lane * H_ + warp] + pall[(lane + 32) * H_ + warp]
                 + pall[(lane + 64) * H_ + warp] + pall[(lane + 96) * H_ + warp];
        #pragma unroll
        for (int off = 16; off; off >>= 1)
            sp += __shfl_xor_sync(0xffffffffu, sp, off);
        if (lane == 0) g_SP[chunk * H_ + warp] = sp;
    }

    // raw p -> g_P
    #pragma unroll
    for (int jj = 0; jj < 2; jj++) {
        int idx = tid + 256 * jj;
        g_P[((size_t)b * U_ + u0) * H_ + idx] = pall[idx];
    }
}

// ---------------- kernel 4: norm = combine (0..127) + aw (128..191) ---------
__global__ void norm_kernel(float* __restrict__ out)
{
    int bx = blockIdx.x;
    int tid = threadIdx.x;   // 512
    int warp = tid >> 5, lane = tid & 31;

    if (bx < 128) {
        int h = bx & 3, b = bx >> 2;
        __shared__ float S_sm;
        if (tid < 32) {
            float sc = g_SP[((size_t)b * NC + lane) * H_ + h];
            #pragma unroll
            for (int off = 16; off; off >>= 1)
                sc += __shfl_xor_sync(0xffffffffu, sc, off);
            if (lane == 0) S_sm = sc;
        }
        __syncthreads();
        float invS = 1.f / S_sm;

        const float* base = g_CTXP + (size_t)b * NC * H_ * D_ + h * D_ + tid;
        float a = 0.f;
        #pragma unroll 8
        for (int c = 0; c < NC; c++)
            a += base[(size_t)c * H_ * D_];
        g_CTX[(size_t)(b * H_ + h) * D_ + tid] = a * invS;
    } else {
        int q = bx - 128;        // 0..63
        int b = q >> 1, half = q & 1;
        __shared__ float S4[4];
        if (warp < 4) {
            float sc = g_SP[((size_t)b * NC + lane) * H_ + warp];
            #pragma unroll
            for (int off = 16; off; off >>= 1)
                sc += __shfl_xor_sync(0xffffffffu, sc, off);
            if (lane == 0) S4[warp] = 0.25f / sc;
        }
        __syncthreads();
        float i0 = S4[0], i1 = S4[1], i2 = S4[2], i3 = S4[3];

        const float4* p = reinterpret_cast<const float4*>(
            g_P + ((size_t)b * U_ + half * 2048) * H_);
        float* o = out + (size_t)B_ * AU_ + (size_t)b * U_ + half * 2048;
        #pragma unroll
        for (int k = 0; k < 4; k++) {
            int u = tid + 512 * k;
            float4 v = p[u];
            o[u] = v.x * i0 + v.y * i1 + v.z * i2 + v.w * i3;
        }
    }
}

// ---------------- kernel 5: out GEMM partials --------------------------------
__global__ void outp_kernel(const float* __restrict__ Wout)
{
    __shared__ float c_sm[32 * 32];   // [b][kl] : 4 KB
    int cg = blockIdx.x, ks = blockIdx.y;
    int tid = threadIdx.x;
    int lane = tid & 31, bg = tid >> 5;   // bg 0..15

    for (int k = tid; k < 32 * 32; k += 512) {
        int bb = k >> 5, kl = k & 31;
        c_sm[k] = g_CTX[(size_t)bb * (H_ * D_) + ks * 32 + kl];
    }
    __syncthreads();

    const float4* wp = reinterpret_cast<const float4*>(
        Wout + ((size_t)ks * 32) * AU_) + cg * 32 + lane;

    float4 acc0 = make_float4(0.f, 0.f, 0.f, 0.f);
    float4 acc1 = make_float4(0.f, 0.f, 0.f, 0.f);
    const float* c0 = c_sm + (2 * bg + 0) * 32;
    const float* c1 = c_sm + (2 * bg + 1) * 32;

    #pragma unroll
    for (int i = 0; i < 32; i++) {
        float4 w = wp[(size_t)i * (AU_ / 4)];
        float a = c0[i], bb = c1[i];
        acc0.x += a * w.x;  acc0.y += a * w.y;
        acc0.z += a * w.z;  acc0.w += a * w.w;
        acc1.x += bb * w.x; acc1.y += bb * w.y;
        acc1.z += bb * w.z; acc1.w += bb * w.w;
    }

    float4* op = reinterpret_cast<float4*>(
        g_OUTP + (size_t)ks * B_ * AU_) + cg * 32 + lane;
    op[(size_t)(2 * bg + 0) * (AU_ / 4)] = acc0;
    op[(size_t)(2 * bg + 1) * (AU_ / 4)] = acc1;
}

// ---------------- kernel 6: out final ----------------------------------------
__global__ void outf_kernel(const float* __restrict__ bout,
                            float* __restrict__ out)
{
    int b = blockIdx.x, t = threadIdx.x;   // 32 x 512
    float v = bout[t];
    #pragma unroll 8
    for (int s = 0; s < KS_; s++)
        v += g_OUTP[((size_t)s * B_ + b) * AU_ + t];
    out[(size_t)b * AU_ + t] = v;
}

// ---------------------------------------------------------------------------
extern "C" void kernel_launch(void* const* d_in, const int* in_sizes, int n_in,
                              void* d_out, int out_size)
{
    const float* dec   = (const float*)d_in[0];
    const float* enc   = (const float*)d_in[1];
    const float* prev  = (const float*)d_in[2];
    const float* Wphi  = (const float*)d_in[3];
    const float* bphi  = (const float*)d_in[4];
    const float* Wpsi  = (const float*)d_in[5];
    // d_in[6] = bpsi: constant along u per (b,h) -> softmax-invariant, unused
    const float* ck    = (const float*)d_in[7];
    const float* Wloc  = (const float*)d_in[8];
    const float* Wout  = (const float*)d_in[9];
    const float* bout  = (const float*)d_in[10];
    float* out = (float*)d_out;

    cudaFuncSetAttribute(fused_kernel,
                         cudaFuncAttributeMaxDynamicSharedMemorySize,
                         SMEM_F_BYTES);

    keff_kernel<<<1, 128>>>(ck, Wloc);                      // idx 0
    phiv_kernel<<<B_ * H_, 256>>>(dec, Wphi, bphi, Wpsi);   // idx 1
    lb_kernel<<<dim3(4, B_), 256>>>(prev);                  // idx 2
    fused_kernel<<<dim3(NC, B_), 256, SMEM_F_BYTES>>>(enc); // idx 3 <- profiled
    norm_kernel<<<192, 512>>>(out);                         // idx 4
    outp_kernel<<<dim3(4, KS_), 512>>>(Wout);               // idx 5
    outf_kernel<<<B_, 512>>>(bout, out);                    // idx 6
}

// round 16
// speedup vs baseline: 1.0199x; 1.0199x over previous
#include <cuda_runtime.h>
#include <cuda_bf16.h>
#include <cstdint>

// Problem constants
#define B_    32
#define U_    4096
#define D_    512
#define H_    4
#define HD_   128
#define CK_   31
#define CF_   32
#define AU_   512

#define UC    128            // u rows per CTA chunk
#define NC    (U_ / UC)      // 32 chunks per batch
#define ST    8              // rows per pipeline stage
#define NSUB  (UC / ST)      // 16
#define KS_   64             // k-slices for the out GEMM (depth 32 each)

// ---------------- scratch (device globals) ----------------------------------
__device__ float g_V[B_ * H_ * D_];
__device__ float g_P[(size_t)B_ * U_ * H_];                 // exp(energy), [b][u][h]
__device__ float g_CTXP[(size_t)B_ * NC * H_ * D_];         // per-chunk ctx partials
__device__ float g_SP[B_ * NC * H_];                        // per-chunk sum of p
__device__ float g_CTX[B_ * H_ * D_];                       // normalized context

// ---------------- PTX helpers -----------------------------------------------
__device__ __forceinline__ uint32_t smem_u32(const void* p) {
    uint32_t a;
    asm("{ .reg .u64 t; cvta.to.shared.u64 t, %1; cvt.u32.u64 %0, t; }"
        : "=r"(a) : "l"(p));
    return a;
}
__device__ __forceinline__ void cp_async16(uint32_t dst, const void* src) {
    asm volatile("cp.async.cg.shared.global [%0], [%1], 16;"
                 :: "r"(dst), "l"(src) : "memory");
}
__device__ __forceinline__ void cp_commit() {
    asm volatile("cp.async.commit_group;" ::: "memory");
}
template <int N>
__device__ __forceinline__ void cp_wait() {
    asm volatile("cp.async.wait_group %0;" :: "n"(N) : "memory");
}
__device__ __forceinline__ void fma2(unsigned long long& d,
                                     unsigned long long a,
                                     unsigned long long b) {
    asm("fma.rn.f32x2 %0, %1, %2, %0;" : "+l"(d) : "l"(a), "l"(b));
}
__device__ __forceinline__ unsigned long long pack2(float lo, float hi) {
    unsigned long long r;
    asm("mov.b64 %0, {%1, %2};" : "=l"(r) : "f"(lo), "f"(hi));
    return r;
}
__device__ __forceinline__ float2 unpack2(unsigned long long v) {
    float2 r;
    asm("mov.b64 {%0, %1}, %2;" : "=f"(r.x), "=f"(r.y) : "l"(v));
    return r;
}

// ---------------- kernel 0: phi & v (prep) -----------------------------------
__global__ void prep_kernel(const float* __restrict__ dec,
                            const float* __restrict__ Wphi,
                            const float* __restrict__ bphi,
                            const float* __restrict__ Wpsi)
{
    __shared__ float dec_sm[D_];
    __shared__ float phi_part[2][HD_];
    __shared__ float phi_sm[HD_];
    int bx = blockIdx.x;
    int b = bx >> 2, h = bx & 3;
    int tid = threadIdx.x;   // 256

    for (int i = tid; i < D_; i += 256) dec_sm[i] = dec[(size_t)b * D_ + i];
    __syncthreads();

    {
        int k = tid & 127, sl = tid >> 7;
        const float* w = Wphi + (size_t)h * D_ * HD_ + (size_t)sl * 256 * HD_ + k;
        const float* ds = dec_sm + sl * 256;
        float a0 = 0.f, a1 = 0.f, a2 = 0.f, a3 = 0.f;
        #pragma unroll 8
        for (int d = 0; d < 256; d += 4) {
            a0 += ds[d + 0] * w[(size_t)(d + 0) * HD_];
            a1 += ds[d + 1] * w[(size_t)(d + 1) * HD_];
            a2 += ds[d + 2] * w[(size_t)(d + 2) * HD_];
            a3 += ds[d + 3] * w[(size_t)(d + 3) * HD_];
        }
        phi_part[sl][k] = (a0 + a1) + (a2 + a3);
    }
    __syncthreads();
    if (tid < HD_)
        phi_sm[tid] = phi_part[0][tid] + phi_part[1][tid] + bphi[h * HD_ + tid];
    __syncthreads();

    for (int e = tid; e < D_; e += 256) {
        const float4* wp = reinterpret_cast<const float4*>(
            Wpsi + ((size_t)h * D_ + e) * HD_);
        float vv = 0.f;
        #pragma unroll 8
        for (int k4 = 0; k4 < HD_ / 4; k4++) {
            float4 ww = wp[k4];
            vv += ww.x * phi_sm[4 * k4 + 0] + ww.y * phi_sm[4 * k4 + 1]
                + ww.z * phi_sm[4 * k4 + 2] + ww.w * phi_sm[4 * k4 + 3];
        }
        g_V[(size_t)bx * D_ + e] = vv;
    }
}

// ---------------- kernel 1: fused energy+exp+context (lb inlined) -----------
// grid (NC=32, B), 256 threads, 2 CTAs/SM, 3-stage pipeline, 1 barrier/subtile.
// Warp split: pair = warp>>1, j = warp&1; rows {pair, pair+4}; heads {2j,2j+1}.
// smem floats (~54.5 KB):
//   tiles 3*ST*D=12288 | pall 512 | lbs 512 | prevs 160 | keffs 128
// ctxred ([4][H][D]=8192 fl) aliases tiles after the main loop.
#define SMEM_F_FLOATS 13600
#define SMEM_F_BYTES (SMEM_F_FLOATS * 4)

__global__ void __launch_bounds__(256, 2)
fused_kernel(const float* __restrict__ enc,
             const float* __restrict__ prev,
             const float* __restrict__ ck,
             const float* __restrict__ Wloc)
{
    extern __shared__ float smem[];
    float* tiles  = smem;                  // 3 x 4096 floats
    float* pall   = smem + 12288;          // [uu][h]
    float* lbs    = smem + 12800;          // [uu][h]
    float* prevs  = smem + 13312;          // UC+30
    float* keffs  = smem + 13472;          // 124
    float* ctxred = smem;                  // ALIAS: post-loop only

    int tid  = threadIdx.x;
    int warp = tid >> 5, lane = tid & 31;
    int pair = warp >> 1, j = warp & 1;
    int b  = blockIdx.y;
    int u0 = blockIdx.x * UC;

    const float* enc_base = enc + ((size_t)b * U_ + u0) * D_;
    uint32_t tiles_s = smem_u32(tiles);

    // prologue: stage subtiles 0, 1
    #pragma unroll
    for (int s = 0; s < 2; s++) {
        uint32_t dst = tiles_s + s * (ST * D_ * 4);
        const float* src = enc_base + s * ST * D_;
        #pragma unroll
        for (int q = 0; q < 4; q++) {
            int idx = tid + 256 * q;
            cp_async16(dst + idx * 16, src + idx * 4);
        }
        cp_commit();
    }

    // stage prev halo + keff (while copies fly)
    for (int i = tid; i < UC + 30; i += 256) {
        int gu = u0 + i - 15;
        prevs[i] = (gu >= 0 && gu < U_) ? prev[(size_t)b * U_ + gu] : 0.f;
    }
    if (tid < CK_ * H_) {
        int k = tid >> 2, hh = tid & 3;
        float s = 0.f;
        #pragma unroll
        for (int f = 0; f < CF_; f++)
            s += ck[k * CF_ + f] * Wloc[f * H_ + hh];
        keffs[tid] = s;
    }
    __syncthreads();

    // compute location bias for the chunk: lbs[uu*H + h]
    #pragma unroll
    for (int q = 0; q < 2; q++) {
        int idx = tid + 256 * q;           // [0,512)
        int uu = idx >> 2, hh = idx & 3;
        float lb = 0.f;
        #pragma unroll
        for (int k = 0; k < CK_; k++)
            lb += prevs[uu + k] * keffs[k * H_ + hh];
        lbs[idx] = lb;
    }

    // v for this warp's 2 heads
    ulonglong2 v2[2][4];
    #pragma unroll
    for (int g = 0; g < 2; g++) {
        const ulonglong2* vp = reinterpret_cast<const ulonglong2*>(
            g_V + (size_t)(b * H_ + 2 * j + g) * D_);
        #pragma unroll
        for (int i = 0; i < 4; i++) v2[g][i] = vp[lane + 32 * i];
    }

    unsigned long long ctx2[2][8];
    #pragma unroll
    for (int g = 0; g < 2; g++)
        #pragma unroll
        for (int i = 0; i < 8; i++) ctx2[g][i] = 0ull;

    for (int s = 0; s < NSUB; s++) {
        if (s < NSUB - 1) cp_wait<1>(); else cp_wait<0>();
        __syncthreads();   // the ONLY barrier per subtile (covers lbs at s=0)

        // prefetch s+2 into slot (s+2)%3 (consumed at s-1; safe)
        if (s + 2 < NSUB) {
            uint32_t dst = tiles_s + ((s + 2) % 3) * (ST * D_ * 4);
            const float* src = enc_base + (s + 2) * ST * D_;
            #pragma unroll
            for (int q = 0; q < 4; q++) {
                int idx = tid + 256 * q;
                cp_async16(dst + idx * 16, src + idx * 4);
            }
            cp_commit();
        }

        const float* tile = tiles + (s % 3) * (ST * D_);
        #pragma unroll
        for (int t = 0; t < 2; t++) {
            int r = pair + 4 * t;
            int uu = s * ST + r;
            const ulonglong2* row =
                reinterpret_cast<const ulonglong2*>(tile + r * D_);
            ulonglong2 X[4];
            #pragma unroll
            for (int i = 0; i < 4; i++) X[i] = row[lane + 32 * i];

            unsigned long long a2h[2] = {0ull, 0ull};
            #pragma unroll
            for (int i = 0; i < 4; i++) {
                fma2(a2h[0], X[i].x, v2[0][i].x);
                fma2(a2h[0], X[i].y, v2[0][i].y);
                fma2(a2h[1], X[i].x, v2[1][i].x);
                fma2(a2h[1], X[i].y, v2[1][i].y);
            }
            float2 f0 = unpack2(a2h[0]), f1 = unpack2(a2h[1]);
            float a0 = f0.x + f0.y, a1 = f1.x + f1.y;
            #pragma unroll
            for (int off = 16; off; off >>= 1) {
                a0 += __shfl_xor_sync(0xffffffffu, a0, off);
                a1 += __shfl_xor_sync(0xffffffffu, a1, off);
            }
            float2 lb = *reinterpret_cast<const float2*>(lbs + uu * H_ + 2 * j);
            float p0 = __expf(a0 + lb.x);
            float p1 = __expf(a1 + lb.y);
            if (lane == 0)
                *reinterpret_cast<float2*>(pall + uu * H_ + 2 * j) =
                    make_float2(p0, p1);
            unsigned long long pp0 = pack2(p0, p0);
            unsigned long long pp1 = pack2(p1, p1);
            #pragma unroll
            for (int i = 0; i < 4; i++) {
                fma2(ctx2[0][2 * i + 0], X[i].x, pp0);
                fma2(ctx2[0][2 * i + 1], X[i].y, pp0);
                fma2(ctx2[1][2 * i + 0], X[i].x, pp1);
                fma2(ctx2[1][2 * i + 1], X[i].y, pp1);
            }
        }
    }
    __syncthreads();   // compute done; tiles memory reusable (ctxred)

    // dump per-warp ctx partials: ctxred[pair][head][e]
    #pragma unroll
    for (int g = 0; g < 2; g++) {
        float4 c[4];
        #pragma unroll
        for (int i = 0; i < 4; i++) {
            float2 lo = unpack2(ctx2[g][2 * i + 0]);
            float2 hi = unpack2(ctx2[g][2 * i + 1]);
            c[i] = make_float4(lo.x, lo.y, hi.x, hi.y);
        }
        float4* cr = reinterpret_cast<float4*>(
            ctxred + (pair * H_ + 2 * j + g) * D_);
        #pragma unroll
        for (int i = 0; i < 4; i++) cr[lane + 32 * i] = c[i];
    }
    __syncthreads();

    size_t chunk = (size_t)b * NC + blockIdx.x;

    // reduce 4 pairs -> g_CTXP
    #pragma unroll
    for (int q = 0; q < 8; q++) {
        int idx = tid + 256 * q;           // [0,2048) == [h][e]
        float sum = ctxred[idx] + ctxred[H_ * D_ + idx]
                  + ctxred[2 * H_ * D_ + idx] + ctxred[3 * H_ * D_ + idx];
        g_CTXP[chunk * (H_ * D_) + idx] = sum;
    }

    // per-chunk sum of p
    if (warp < H_) {
        float sp = pall[lane * H_ + warp] + pall[(lane + 32) * H_ + warp]
                 + pall[(lane + 64) * H_ + warp] + pall[(lane + 96) * H_ + warp];
        #pragma unroll
        for (int off = 16; off; off >>= 1)
            sp += __shfl_xor_sync(0xffffffffu, sp, off);
        if (lane == 0) g_SP[chunk * H_ + warp] = sp;
    }

    // raw p -> g_P
    #pragma unroll
    for (int jj = 0; jj < 2; jj++) {
        int idx = tid + 256 * jj;
        g_P[((size_t)b * U_ + u0) * H_ + idx] = pall[idx];
    }
}

// ---------------- kernel 2: norm = combine | aw | bout-init ------------------
// grid 224: [0,128) combine, [128,192) aw, [192,224) bout-init
__global__ void norm_kernel(const float* __restrict__ bout,
                            float* __restrict__ out)
{
    int bx = blockIdx.x;
    int tid = threadIdx.x;   // 512
    int warp = tid >> 5, lane = tid & 31;

    if (bx < 128) {
        int h = bx & 3, b = bx >> 2;
        __shared__ float S_sm;
        if (tid < 32) {
            float sc = g_SP[((size_t)b * NC + lane) * H_ + h];
            #pragma unroll
            for (int off = 16; off; off >>= 1)
                sc += __shfl_xor_sync(0xffffffffu, sc, off);
            if (lane == 0) S_sm = sc;
        }
        __syncthreads();
        float invS = 1.f / S_sm;

        const float* base = g_CTXP + (size_t)b * NC * H_ * D_ + h * D_ + tid;
        float a = 0.f;
        #pragma unroll 8
        for (int c = 0; c < NC; c++)
            a += base[(size_t)c * H_ * D_];
        g_CTX[(size_t)(b * H_ + h) * D_ + tid] = a * invS;
    } else if (bx < 192) {
        int q = bx - 128;        // 0..63
        int b = q >> 1, half = q & 1;
        __shared__ float S4[4];
        if (warp < 4) {
            float sc = g_SP[((size_t)b * NC + lane) * H_ + warp];
            #pragma unroll
            for (int off = 16; off; off >>= 1)
                sc += __shfl_xor_sync(0xffffffffu, sc, off);
            if (lane == 0) S4[warp] = 0.25f / sc;
        }
        __syncthreads();
        float i0 = S4[0], i1 = S4[1], i2 = S4[2], i3 = S4[3];

        const float4* p = reinterpret_cast<const float4*>(
            g_P + ((size_t)b * U_ + half * 2048) * H_);
        float* o = out + (size_t)B_ * AU_ + (size_t)b * U_ + half * 2048;
        #pragma unroll
        for (int k = 0; k < 4; k++) {
            int u = tid + 512 * k;
            float4 v = p[u];
            o[u] = v.x * i0 + v.y * i1 + v.z * i2 + v.w * i3;
        }
    } else {
        int b = bx - 192;        // 0..31: seed out with bias
        out[(size_t)b * AU_ + tid] = bout[tid];
    }
}

// ---------------- kernel 3 (PROFILED): out GEMM, atomic accumulate ----------
// grid (4 colgroups of 128, KS_=64 k-slices of 32), block 512 = 32 lanes x 16 bg
__global__ void outp_kernel(const float* __restrict__ Wout,
                            float* __restrict__ out)
{
    __shared__ float c_sm[32 * 32];   // [b][kl] : 4 KB
    int cg = blockIdx.x, ks = blockIdx.y;
    int tid = threadIdx.x;
    int lane = tid & 31, bg = tid >> 5;   // bg 0..15

    for (int k = tid; k < 32 * 32; k += 512) {
        int bb = k >> 5, kl = k & 31;
        c_sm[k] = g_CTX[(size_t)bb * (H_ * D_) + ks * 32 + kl];
    }
    __syncthreads();

    const float4* wp = reinterpret_cast<const float4*>(
        Wout + ((size_t)ks * 32) * AU_) + cg * 32 + lane;

    float4 acc0 = make_float4(0.f, 0.f, 0.f, 0.f);
    float4 acc1 = make_float4(0.f, 0.f, 0.f, 0.f);
    const float* c0 = c_sm + (2 * bg + 0) * 32;
    const float* c1 = c_sm + (2 * bg + 1) * 32;

    #pragma unroll
    for (int i = 0; i < 32; i++) {
        float4 w = wp[(size_t)i * (AU_ / 4)];
        float a = c0[i], bb = c1[i];
        acc0.x += a * w.x;  acc0.y += a * w.y;
        acc0.z += a * w.z;  acc0.w += a * w.w;
        acc1.x += bb * w.x; acc1.y += bb * w.y;
        acc1.z += bb * w.z; acc1.w += bb * w.w;
    }

    int col = cg * 128 + lane * 4;
    float* o0 = out + (size_t)(2 * bg + 0) * AU_ + col;
    float* o1 = out + (size_t)(2 * bg + 1) * AU_ + col;
    atomicAdd(o0 + 0, acc0.x); atomicAdd(o0 + 1, acc0.y);
    atomicAdd(o0 + 2, acc0.z); atomicAdd(o0 + 3, acc0.w);
    atomicAdd(o1 + 0, acc1.x); atomicAdd(o1 + 1, acc1.y);
    atomicAdd(o1 + 2, acc1.z); atomicAdd(o1 + 3, acc1.w);
}

// ---------------------------------------------------------------------------
extern "C" void kernel_launch(void* const* d_in, const int* in_sizes, int n_in,
                              void* d_out, int out_size)
{
    const float* dec   = (const float*)d_in[0];
    const float* enc   = (const float*)d_in[1];
    const float* prev  = (const float*)d_in[2];
    const float* Wphi  = (const float*)d_in[3];
    const float* bphi  = (const float*)d_in[4];
    const float* Wpsi  = (const float*)d_in[5];
    // d_in[6] = bpsi: constant along u per (b,h) -> softmax-invariant, unused
    const float* ck    = (const float*)d_in[7];
    const float* Wloc  = (const float*)d_in[8];
    const float* Wout  = (const float*)d_in[9];
    const float* bout  = (const float*)d_in[10];
    float* out = (float*)d_out;

    cudaFuncSetAttribute(fused_kernel,
                         cudaFuncAttributeMaxDynamicSharedMemorySize,
                         SMEM_F_BYTES);

    prep_kernel<<<128, 256>>>(dec, Wphi, bphi, Wpsi);                  // idx 0
    fused_kernel<<<dim3(NC, B_), 256, SMEM_F_BYTES>>>(enc, prev, ck, Wloc); // idx 1
    norm_kernel<<<224, 512>>>(bout, out);                              // idx 2
    outp_kernel<<<dim3(4, KS_), 512>>>(Wout, out);                     // idx 3 <- profiled
}

// round 17
// speedup vs baseline: 1.1435x; 1.1212x over previous
#include <cuda_runtime.h>
#include <cuda_bf16.h>
#include <cstdint>

// Problem constants
#define B_    32
#define U_    4096
#define D_    512
#define H_    4
#define HD_   128
#define CK_   31
#define CF_   32
#define AU_   512

#define UC    128            // u rows per CTA chunk
#define NC    (U_ / UC)      // 32 chunks per batch
#define ST    8              // rows per pipeline stage
#define NSUB  (UC / ST)      // 16
#define KS_   64             // k-slices for the out GEMM (depth 32 each)

// ---------------- scratch (device globals) ----------------------------------
__device__ float g_V[B_ * H_ * D_];
__device__ float g_LB[(size_t)B_ * U_ * H_];                // location bias [b][u][h]
__device__ float g_P[(size_t)B_ * U_ * H_];                 // exp(energy), [b][u][h]
__device__ float g_CTXP[(size_t)B_ * NC * H_ * D_];         // per-chunk ctx partials
__device__ float g_SP[B_ * NC * H_];                        // per-chunk sum of p
__device__ float g_CTX[B_ * H_ * D_];                       // normalized context
__device__ float g_OUTP[KS_ * B_ * AU_];                    // out GEMM partials

// ---------------- PTX helpers -----------------------------------------------
__device__ __forceinline__ uint32_t smem_u32(const void* p) {
    uint32_t a;
    asm("{ .reg .u64 t; cvta.to.shared.u64 t, %1; cvt.u32.u64 %0, t; }"
        : "=r"(a) : "l"(p));
    return a;
}
__device__ __forceinline__ void cp_async16(uint32_t dst, const void* src) {
    asm volatile("cp.async.cg.shared.global [%0], [%1], 16;"
                 :: "r"(dst), "l"(src) : "memory");
}
__device__ __forceinline__ void cp_commit() {
    asm volatile("cp.async.commit_group;" ::: "memory");
}
template <int N>
__device__ __forceinline__ void cp_wait() {
    asm volatile("cp.async.wait_group %0;" :: "n"(N) : "memory");
}
__device__ __forceinline__ void fma2(unsigned long long& d,
                                     unsigned long long a,
                                     unsigned long long b) {
    asm("fma.rn.f32x2 %0, %1, %2, %0;" : "+l"(d) : "l"(a), "l"(b));
}
__device__ __forceinline__ unsigned long long pack2(float lo, float hi) {
    unsigned long long r;
    asm("mov.b64 %0, {%1, %2};" : "=l"(r) : "f"(lo), "f"(hi));
    return r;
}
__device__ __forceinline__ float2 unpack2(unsigned long long v) {
    float2 r;
    asm("mov.b64 {%0, %1}, %2;" : "=f"(r.x), "=f"(r.y) : "l"(v));
    return r;
}

// ---------------- kernel 0: prep = phiv (blocks 0..127) + lb (128..255) -----
__global__ void prep_kernel(const float* __restrict__ dec,
                            const float* __restrict__ Wphi,
                            const float* __restrict__ bphi,
                            const float* __restrict__ Wpsi,
                            const float* __restrict__ ck,
                            const float* __restrict__ Wloc,
                            const float* __restrict__ prev)
{
    __shared__ float sm[1184];
    int bx = blockIdx.x;
    int tid = threadIdx.x;   // 256

    if (bx < 128) {
        float* dec_sm   = sm;            // 512
        float* phi_part = sm + 512;      // 2*128
        float* phi_sm   = sm + 768;      // 128
        int b = bx >> 2, h = bx & 3;

        for (int i = tid; i < D_; i += 256) dec_sm[i] = dec[(size_t)b * D_ + i];
        __syncthreads();

        {
            int k = tid & 127, sl = tid >> 7;
            const float* w = Wphi + (size_t)h * D_ * HD_ + (size_t)sl * 256 * HD_ + k;
            const float* ds = dec_sm + sl * 256;
            float a0 = 0.f, a1 = 0.f, a2 = 0.f, a3 = 0.f;
            #pragma unroll 8
            for (int d = 0; d < 256; d += 4) {
                a0 += ds[d + 0] * w[(size_t)(d + 0) * HD_];
                a1 += ds[d + 1] * w[(size_t)(d + 1) * HD_];
                a2 += ds[d + 2] * w[(size_t)(d + 2) * HD_];
                a3 += ds[d + 3] * w[(size_t)(d + 3) * HD_];
            }
            phi_part[sl * 128 + k] = (a0 + a1) + (a2 + a3);
        }
        __syncthreads();
        if (tid < HD_)
            phi_sm[tid] = phi_part[tid] + phi_part[128 + tid] + bphi[h * HD_ + tid];
        __syncthreads();

        for (int e = tid; e < D_; e += 256) {
            const float4* wp = reinterpret_cast<const float4*>(
                Wpsi + ((size_t)h * D_ + e) * HD_);
            float vv = 0.f;
            #pragma unroll 8
            for (int k4 = 0; k4 < HD_ / 4; k4++) {
                float4 ww = wp[k4];
                vv += ww.x * phi_sm[4 * k4 + 0] + ww.y * phi_sm[4 * k4 + 1]
                    + ww.z * phi_sm[4 * k4 + 2] + ww.w * phi_sm[4 * k4 + 3];
            }
            g_V[(size_t)bx * D_ + e] = vv;
        }
    } else {
        float* prevs = sm;               // 1024 + 30
        float* keffs = sm + 1056;        // 124
        int idx = bx - 128;
        int z = idx & 3, b = idx >> 2;
        int ubase = z * 1024;

        if (tid < CK_ * H_) {
            int k = tid >> 2, h = tid & 3;
            float s = 0.f;
            #pragma unroll
            for (int f = 0; f < CF_; f++)
                s += ck[k * CF_ + f] * Wloc[f * H_ + h];
            keffs[tid] = s;
        }
        for (int i = tid; i < 1024 + CK_ - 1; i += 256) {
            int gu = ubase + i - 15;
            prevs[i] = (gu >= 0 && gu < U_) ? prev[(size_t)b * U_ + gu] : 0.f;
        }
        __syncthreads();

        float4* outp = reinterpret_cast<float4*>(
            g_LB + ((size_t)b * U_ + ubase) * H_);
        #pragma unroll
        for (int q = 0; q < 4; q++) {
            int ul = tid + 256 * q;
            float l0 = 0.f, l1 = 0.f, l2 = 0.f, l3 = 0.f;
            #pragma unroll
            for (int k = 0; k < CK_; k++) {
                float pv = prevs[ul + k];
                l0 += pv * keffs[k * H_ + 0];
                l1 += pv * keffs[k * H_ + 1];
                l2 += pv * keffs[k * H_ + 2];
                l3 += pv * keffs[k * H_ + 3];
            }
            outp[ul] = make_float4(l0, l1, l2, l3);
        }
    }
}

// ---------------- kernel 1: fused energy+exp+context ------------------------
// grid (NC=32, B), 256 threads, 2 CTAs/SM, 3-stage pipeline, 1 barrier/subtile.
// Warp split: pair = warp>>1, j = warp&1; rows {pair, pair+4}; heads {2j,2j+1}.
// smem floats (52 KB): tiles 3*ST*D=12288 | pall 512 | lbs 512
// ctxred ([4][H][D]=8192 fl) aliases tiles after the main loop.
#define SMEM_F_FLOATS 13312
#define SMEM_F_BYTES (SMEM_F_FLOATS * 4)

__global__ void __launch_bounds__(256, 2)
fused_kernel(const float* __restrict__ enc)
{
    extern __shared__ float smem[];
    float* tiles  = smem;                  // 3 x 4096 floats
    float* pall   = smem + 12288;          // [uu][h]
    float* lbs    = smem + 12800;          // [uu][h]
    float* ctxred = smem;                  // ALIAS: post-loop only

    int tid  = threadIdx.x;
    int warp = tid >> 5, lane = tid & 31;
    int pair = warp >> 1, j = warp & 1;
    int b  = blockIdx.y;
    int u0 = blockIdx.x * UC;

    const float* enc_base = enc + ((size_t)b * U_ + u0) * D_;
    uint32_t tiles_s = smem_u32(tiles);

    // prologue: stage subtiles 0, 1
    #pragma unroll
    for (int s = 0; s < 2; s++) {
        uint32_t dst = tiles_s + s * (ST * D_ * 4);
        const float* src = enc_base + s * ST * D_;
        #pragma unroll
        for (int q = 0; q < 4; q++) {
            int idx = tid + 256 * q;
            cp_async16(dst + idx * 16, src + idx * 4);
        }
        cp_commit();
    }

    // stage lb for the chunk
    #pragma unroll
    for (int q = 0; q < 2; q++) {
        int idx = tid + 256 * q;
        lbs[idx] = g_LB[((size_t)b * U_ + u0) * H_ + idx];
    }

    // v for this warp's 2 heads, packed pairs
    ulonglong2 v2[2][4];
    #pragma unroll
    for (int g = 0; g < 2; g++) {
        const ulonglong2* vp = reinterpret_cast<const ulonglong2*>(
            g_V + (size_t)(b * H_ + 2 * j + g) * D_);
        #pragma unroll
        for (int i = 0; i < 4; i++) v2[g][i] = vp[lane + 32 * i];
    }

    unsigned long long ctx2[2][8];
    #pragma unroll
    for (int g = 0; g < 2; g++)
        #pragma unroll
        for (int i = 0; i < 8; i++) ctx2[g][i] = 0ull;

    for (int s = 0; s < NSUB; s++) {
        if (s < NSUB - 1) cp_wait<1>(); else cp_wait<0>();
        __syncthreads();   // the ONLY barrier per subtile

        // prefetch s+2 into slot (s+2)%3 (consumed at s-1; safe)
        if (s + 2 < NSUB) {
            uint32_t dst = tiles_s + ((s + 2) % 3) * (ST * D_ * 4);
            const float* src = enc_base + (s + 2) * ST * D_;
            #pragma unroll
            for (int q = 0; q < 4; q++) {
                int idx = tid + 256 * q;
                cp_async16(dst + idx * 16, src + idx * 4);
            }
            cp_commit();
        }

        const float* tile = tiles + (s % 3) * (ST * D_);
        #pragma unroll
        for (int t = 0; t < 2; t++) {
            int r = pair + 4 * t;          // rows pair, pair+4
            int uu = s * ST + r;
            const ulonglong2* row =
                reinterpret_cast<const ulonglong2*>(tile + r * D_);
            ulonglong2 X[4];
            #pragma unroll
            for (int i = 0; i < 4; i++) X[i] = row[lane + 32 * i];

            unsigned long long a2h[2] = {0ull, 0ull};
            #pragma unroll
            for (int i = 0; i < 4; i++) {
                fma2(a2h[0], X[i].x, v2[0][i].x);
                fma2(a2h[0], X[i].y, v2[0][i].y);
                fma2(a2h[1], X[i].x, v2[1][i].x);
                fma2(a2h[1], X[i].y, v2[1][i].y);
            }
            float2 f0 = unpack2(a2h[0]), f1 = unpack2(a2h[1]);
            float a0 = f0.x + f0.y, a1 = f1.x + f1.y;
            #pragma unroll
            for (int off = 16; off; off >>= 1) {
                a0 += __shfl_xor_sync(0xffffffffu, a0, off);
                a1 += __shfl_xor_sync(0xffffffffu, a1, off);
            }
            float2 lb = *reinterpret_cast<const float2*>(lbs + uu * H_ + 2 * j);
            float p0 = __expf(a0 + lb.x);
            float p1 = __expf(a1 + lb.y);
            if (lane == 0)
                *reinterpret_cast<float2*>(pall + uu * H_ + 2 * j) =
                    make_float2(p0, p1);
            unsigned long long pp0 = pack2(p0, p0);
            unsigned long long pp1 = pack2(p1, p1);
            #pragma unroll
            for (int i = 0; i < 4; i++) {
                fma2(ctx2[0][2 * i + 0], X[i].x, pp0);
                fma2(ctx2[0][2 * i + 1], X[i].y, pp0);
                fma2(ctx2[1][2 * i + 0], X[i].x, pp1);
                fma2(ctx2[1][2 * i + 1], X[i].y, pp1);
            }
        }
    }
    __syncthreads();   // compute done; tiles memory reusable (ctxred)

    // dump per-warp ctx partials: ctxred[pair][head][e]
    #pragma unroll
    for (int g = 0; g < 2; g++) {
        float4 c[4];
        #pragma unroll
        for (int i = 0; i < 4; i++) {
            float2 lo = unpack2(ctx2[g][2 * i + 0]);
            float2 hi = unpack2(ctx2[g][2 * i + 1]);
            c[i] = make_float4(lo.x, lo.y, hi.x, hi.y);
        }
        float4* cr = reinterpret_cast<float4*>(
            ctxred + (pair * H_ + 2 * j + g) * D_);
        #pragma unroll
        for (int i = 0; i < 4; i++) cr[lane + 32 * i] = c[i];
    }
    __syncthreads();

    size_t chunk = (size_t)b * NC + blockIdx.x;

    // reduce 4 pairs -> g_CTXP
    #pragma unroll
    for (int q = 0; q < 8; q++) {
        int idx = tid + 256 * q;           // [0,2048) == [h][e]
        float sum = ctxred[idx] + ctxred[H_ * D_ + idx]
                  + ctxred[2 * H_ * D_ + idx] + ctxred[3 * H_ * D_ + idx];
        g_CTXP[chunk * (H_ * D_) + idx] = sum;
    }

    // per-chunk sum of p
    if (warp < H_) {
        float sp = pall[lane * H_ + warp] + pall[(lane + 32) * H_ + warp]
                 + pall[(lane + 64) * H_ + warp] + pall[(lane + 96) * H_ + warp];
        #pragma unroll
        for (int off = 16; off; off >>= 1)
            sp += __shfl_xor_sync(0xffffffffu, sp, off);
        if (lane == 0) g_SP[chunk * H_ + warp] = sp;
    }

    // raw p -> g_P
    #pragma unroll
    for (int jj = 0; jj < 2; jj++) {
        int idx = tid + 256 * jj;
        g_P[((size_t)b * U_ + u0) * H_ + idx] = pall[idx];
    }
}

// ---------------- kernel 2: norm = combine (0..127) + aw (128..191) ---------
__global__ void norm_kernel(float* __restrict__ out)
{
    int bx = blockIdx.x;
    int tid = threadIdx.x;   // 512
    int warp = tid >> 5, lane = tid & 31;

    if (bx < 128) {
        int h = bx & 3, b = bx >> 2;
        __shared__ float S_sm;
        if (tid < 32) {
            float sc = g_SP[((size_t)b * NC + lane) * H_ + h];
            #pragma unroll
            for (int off = 16; off; off >>= 1)
                sc += __shfl_xor_sync(0xffffffffu, sc, off);
            if (lane == 0) S_sm = sc;
        }
        __syncthreads();
        float invS = 1.f / S_sm;

        const float* base = g_CTXP + (size_t)b * NC * H_ * D_ + h * D_ + tid;
        float a = 0.f;
        // load-batched: 4 batches of 8 resident loads -> MLP 8
        #pragma unroll
        for (int cb = 0; cb < 4; cb++) {
            float r[8];
            #pragma unroll
            for (int i = 0; i < 8; i++)
                r[i] = base[(size_t)(cb * 8 + i) * H_ * D_];
            #pragma unroll
            for (int i = 0; i < 8; i++) a += r[i];
        }
        g_CTX[(size_t)(b * H_ + h) * D_ + tid] = a * invS;
    } else {
        int q = bx - 128;        // 0..63
        int b = q >> 1, half = q & 1;
        __shared__ float S4[4];
        if (warp < 4) {
            float sc = g_SP[((size_t)b * NC + lane) * H_ + warp];
            #pragma unroll
            for (int off = 16; off; off >>= 1)
                sc += __shfl_xor_sync(0xffffffffu, sc, off);
            if (lane == 0) S4[warp] = 0.25f / sc;
        }
        __syncthreads();
        float i0 = S4[0], i1 = S4[1], i2 = S4[2], i3 = S4[3];

        const float4* p = reinterpret_cast<const float4*>(
            g_P + ((size_t)b * U_ + half * 2048) * H_);
        float* o = out + (size_t)B_ * AU_ + (size_t)b * U_ + half * 2048;
        #pragma unroll
        for (int k = 0; k < 4; k++) {
            int u = tid + 512 * k;
            float4 v = p[u];
            o[u] = v.x * i0 + v.y * i1 + v.z * i2 + v.w * i3;
        }
    }
}

// ---------------- kernel 3 (PROFILED): out GEMM partials --------------------
// grid (4 colgroups of 128, KS_=64 k-slices of 32), block 512 = 32 lanes x 16 bg.
// Load-batched Wout: w[8] resident per batch -> MLP 8 (was ~4 at 36 regs).
__global__ void __launch_bounds__(512)
outp_kernel(const float* __restrict__ Wout)
{
    __shared__ float c_sm[32 * 32];   // [b][kl] : 4 KB
    int cg = blockIdx.x, ks = blockIdx.y;
    int tid = threadIdx.x;
    int lane = tid & 31, bg = tid >> 5;   // bg 0..15

    for (int k = tid; k < 32 * 32; k += 512) {
        int bb = k >> 5, kl = k & 31;
        c_sm[k] = g_CTX[(size_t)bb * (H_ * D_) + ks * 32 + kl];
    }
    __syncthreads();

    const float4* wp = reinterpret_cast<const float4*>(
        Wout + ((size_t)ks * 32) * AU_) + cg * 32 + lane;

    float4 acc0 = make_float4(0.f, 0.f, 0.f, 0.f);
    float4 acc1 = make_float4(0.f, 0.f, 0.f, 0.f);
    const float* c0 = c_sm + (2 * bg + 0) * 32;
    const float* c1 = c_sm + (2 * bg + 1) * 32;

    #pragma unroll
    for (int ib = 0; ib < 4; ib++) {
        float4 w[8];
        #pragma unroll
        for (int i = 0; i < 8; i++)
            w[i] = wp[(size_t)(ib * 8 + i) * (AU_ / 4)];
        #pragma unroll
        for (int i = 0; i < 8; i++) {
            float a = c0[ib * 8 + i], bb = c1[ib * 8 + i];
            acc0.x += a * w[i].x;  acc0.y += a * w[i].y;
            acc0.z += a * w[i].z;  acc0.w += a * w[i].w;
            acc1.x += bb * w[i].x; acc1.y += bb * w[i].y;
            acc1.z += bb * w[i].z; acc1.w += bb * w[i].w;
        }
    }

    float4* op = reinterpret_cast<float4*>(
        g_OUTP + (size_t)ks * B_ * AU_) + cg * 32 + lane;
    op[(size_t)(2 * bg + 0) * (AU_ / 4)] = acc0;
    op[(size_t)(2 * bg + 1) * (AU_ / 4)] = acc1;
}

// ---------------- kernel 4: out final ----------------------------------------
__global__ void outf_kernel(const float* __restrict__ bout,
                            float* __restrict__ out)
{
    int b = blockIdx.x, t = threadIdx.x;   // 32 x 512
    float v = bout[t];
    #pragma unroll 8
    for (int s = 0; s < KS_; s++)
        v += g_OUTP[((size_t)s * B_ + b) * AU_ + t];
    out[(size_t)b * AU_ + t] = v;
}

// ---------------------------------------------------------------------------
extern "C" void kernel_launch(void* const* d_in, const int* in_sizes, int n_in,
                              void* d_out, int out_size)
{
    const float* dec   = (const float*)d_in[0];
    const float* enc   = (const float*)d_in[1];
    const float* prev  = (const float*)d_in[2];
    const float* Wphi  = (const float*)d_in[3];
    const float* bphi  = (const float*)d_in[4];
    const float* Wpsi  = (const float*)d_in[5];
    // d_in[6] = bpsi: constant along u per (b,h) -> softmax-invariant, unused
    const float* ck    = (const float*)d_in[7];
    const float* Wloc  = (const float*)d_in[8];
    const float* Wout  = (const float*)d_in[9];
    const float* bout  = (const float*)d_in[10];
    float* out = (float*)d_out;

    cudaFuncSetAttribute(fused_kernel,
                         cudaFuncAttributeMaxDynamicSharedMemorySize,
                         SMEM_F_BYTES);

    prep_kernel<<<256, 256>>>(dec, Wphi, bphi, Wpsi, ck, Wloc, prev); // idx 0
    fused_kernel<<<dim3(NC, B_), 256, SMEM_F_BYTES>>>(enc);           // idx 1
    norm_kernel<<<192, 512>>>(out);                                   // idx 2
    outp_kernel<<<dim3(4, KS_), 512>>>(Wout);                         // idx 3 <- profiled
    outf_kernel<<<B_, 512>>>(bout, out);                              // idx 4
}